// round 10
// baseline (speedup 1.0000x reference)
#include <cuda_runtime.h>
#include <cstdint>

#define BB 4
#define NN 2048
#define CC 1024
#define HH 16
#define DD 64
#define MM (BB*NN)          // 8192

// Scratch layouts (all tf32-rounded, post-LN for q,k; q pre-scaled by 0.125*log2e):
//   g_q, g_k : [bh][token][64 d], d-columns sigma-permuted within 8-groups
//   g_v      : [bh][64 d][2048 tokens], tokens sigma-permuted within 8-groups
__device__ float g_q[(size_t)MM * CC];
__device__ float g_k[(size_t)MM * CC];
__device__ float g_v[(size_t)MM * CC];
// tf32-pre-rounded copies of inputs (read by proj via cp.async)
__device__ float g_x1t[(size_t)MM * CC];
__device__ float g_x2t[(size_t)MM * CC];
__device__ float g_wqt[(size_t)CC * CC];
__device__ float g_wkvt[(size_t)CC * 2 * CC];

// ---------------------------------------------------------------------------
// helpers
// ---------------------------------------------------------------------------
__device__ __forceinline__ float f2tf(float x) {
    uint32_t u;
    asm("cvt.rna.tf32.f32 %0, %1;" : "=r"(u) : "f"(x));
    return __uint_as_float(u);
}

__device__ __forceinline__ float ex2(float x) {
    float r;
    asm("ex2.approx.ftz.f32 %0, %1;" : "=f"(r) : "f"(x));
    return r;
}

__device__ __forceinline__ uint32_t smem_u32(const void* p) {
    uint32_t a;
    asm("{ .reg .u64 t; cvta.to.shared.u64 t, %1; cvt.u32.u64 %0, t; }" : "=r"(a) : "l"(p));
    return a;
}

__device__ __forceinline__ void cp16(uint32_t dst, const void* src) {
    asm volatile("cp.async.cg.shared.global [%0], [%1], 16;" :: "r"(dst), "l"(src));
}
__device__ __forceinline__ void cp_commit() { asm volatile("cp.async.commit_group;"); }
__device__ __forceinline__ void cp_wait0()  { asm volatile("cp.async.wait_group 0;"); }
__device__ __forceinline__ void cp_wait1()  { asm volatile("cp.async.wait_group 1;"); }

__device__ __forceinline__ void mma8(float c[4], const uint32_t a[4], const uint32_t b[2]) {
    asm volatile(
        "mma.sync.aligned.m16n8k8.row.col.f32.tf32.tf32.f32 "
        "{%0,%1,%2,%3}, {%4,%5,%6,%7}, {%8,%9}, {%0,%1,%2,%3};\n"
        : "+f"(c[0]), "+f"(c[1]), "+f"(c[2]), "+f"(c[3])
        : "r"(a[0]), "r"(a[1]), "r"(a[2]), "r"(a[3]), "r"(b[0]), "r"(b[1]));
}

// ---------------------------------------------------------------------------
// Elementwise tf32 pre-rounding pass
// ---------------------------------------------------------------------------
__global__ __launch_bounds__(256) void prep_kernel(const float* __restrict__ src,
                                                   float* __restrict__ dst, int n4)
{
    int i = blockIdx.x * 256 + threadIdx.x;
    if (i < n4) {
        float4 v = ((const float4*)src)[i];
        ((float4*)dst)[i] = make_float4(f2tf(v.x), f2tf(v.y), f2tf(v.z), f2tf(v.w));
    }
}

// ---------------------------------------------------------------------------
// Projection GEMM (q + kv in one launch), tf32 MMA, cp.async double-buffered.
// Block tile 128 rows x 128 cols (2 heads); 4 warps, each 64x64 (wm x wn).
// Epilogue: bias + per-head LayerNorm (q,k), q scaled by 0.125*log2(e),
// stores in attention-ready permuted layouts (see globals above).
// ---------------------------------------------------------------------------
#define PROJ_SMEM ((2*128*36 + 2*32*136) * 4)   // 71680 bytes

__global__ __launch_bounds__(128, 3) void proj_kernel(
    const float* __restrict__ bq, const float* __restrict__ bkv,
    const float* __restrict__ gamq, const float* __restrict__ betq,
    const float* __restrict__ gamk, const float* __restrict__ betk)
{
    extern __shared__ float psm[];
    float (*As)[36]  = (float(*)[36])psm;                   // [2*128][36]
    float (*Bs)[136] = (float(*)[136])(psm + 2 * 128 * 36); // [2*32][136]

    int tid  = threadIdx.x;
    int wid  = tid >> 5, lane = tid & 31;
    int grp  = lane >> 2, l4 = lane & 3;
    int wm   = wid >> 1, wn = wid & 1;
    int m0   = blockIdx.y << 7;
    int cb   = blockIdx.x;            // 0..23

    const float *A, *W, *bias, *gam, *bet;
    float* Out; int ld, n0, do_ln, is_q, is_v;
    if (cb < 8) {
        A = g_x1t; W = g_wqt; bias = bq; ld = CC; n0 = cb << 7;
        Out = g_q; do_ln = 1; is_q = 1; is_v = 0; gam = gamq; bet = betq;
    } else {
        int c2 = cb - 8;
        A = g_x2t; W = g_wkvt; bias = bkv; ld = 2 * CC; n0 = c2 << 7; is_q = 0;
        if (c2 < 8) { Out = g_k; do_ln = 1; is_v = 0; gam = gamk; bet = betk; }
        else        { Out = g_v; do_ln = 0; is_v = 1; gam = gamq; bet = betq; }
    }
    int n0w = n0 + (wn << 6);
    int head = (is_v ? (n0w - 1024) : n0w) >> 6;

    float c[4][8][4];
    #pragma unroll
    for (int mf = 0; mf < 4; mf++)
        #pragma unroll
        for (int nf = 0; nf < 8; nf++)
            #pragma unroll
            for (int i = 0; i < 4; i++) c[mf][nf][i] = 0.f;

    uint32_t as_u = smem_u32(As), bs_u = smem_u32(Bs);
    int ar = tid >> 3, ac = tid & 7;
    int br = tid >> 5, bc = tid & 31;
    const float* Ap = A + (size_t)(m0 + ar) * CC + (ac << 2);
    const float* Wp = W + (size_t)br * ld + n0 + (bc << 2);

    #pragma unroll
    for (int i = 0; i < 8; i++) {
        cp16(as_u + ((ar + (i << 4)) * 36 + (ac << 2)) * 4, Ap + (size_t)(i << 4) * CC);
        cp16(bs_u + ((br + (i << 2)) * 136 + (bc << 2)) * 4, Wp + (size_t)(i << 2) * ld);
    }
    cp_commit();

    for (int ch = 0; ch < 32; ch++) {
        int buf = ch & 1;
        if (ch < 31) {
            int k0 = (ch + 1) << 5;
            int ob = buf ^ 1;
            #pragma unroll
            for (int i = 0; i < 8; i++) {
                cp16(as_u + (((ob << 7) + ar + (i << 4)) * 36 + (ac << 2)) * 4,
                     Ap + (size_t)(i << 4) * CC + k0);
                cp16(bs_u + (((ob << 5) + br + (i << 2)) * 136 + (bc << 2)) * 4,
                     Wp + (size_t)(k0 + (i << 2)) * ld);
            }
            cp_commit();
            cp_wait1();
        } else {
            cp_wait0();
        }
        __syncthreads();

        float (*Ab)[36]  = &As[buf << 7];
        float (*Bb)[136] = &Bs[buf << 5];
        #pragma unroll
        for (int ks = 0; ks < 4; ks++) {
            int k8 = ks << 3;
            uint32_t a[4][4];
            #pragma unroll
            for (int mf = 0; mf < 4; mf++) {
                int r = (wm << 6) + (mf << 4) + grp;
                a[mf][0] = __float_as_uint(Ab[r][k8 + l4]);
                a[mf][1] = __float_as_uint(Ab[r + 8][k8 + l4]);
                a[mf][2] = __float_as_uint(Ab[r][k8 + l4 + 4]);
                a[mf][3] = __float_as_uint(Ab[r + 8][k8 + l4 + 4]);
            }
            #pragma unroll
            for (int nf = 0; nf < 8; nf++) {
                int n = (wn << 6) + (nf << 3) + grp;
                uint32_t b[2];
                b[0] = __float_as_uint(Bb[k8 + l4][n]);
                b[1] = __float_as_uint(Bb[k8 + l4 + 4][n]);
                #pragma unroll
                for (int mf = 0; mf < 4; mf++)
                    mma8(c[mf][nf], a[mf], b);
            }
        }
        __syncthreads();
    }

    // Epilogue: bias + (optional) LN + (q) log2 scale + permuted tf32 store
    const float SC = 0.18033688011112042f;     // 0.125 * log2(e)
    // sigma positions for within-8-group d columns (2*l4, 2*l4+1)
    int p0 = (((l4 << 1) & 3) << 1) | (l4 >> 1);        // {0,4,1,5}
    int p1 = ((((l4 << 1) + 1) & 3) << 1) | (l4 >> 1);  // {2,6,3,7}
    int sg = ((grp & 3) << 1) | (grp >> 2);             // token sigma for V

    #pragma unroll
    for (int mf = 0; mf < 4; mf++) {
        float s0 = 0.f, s1 = 0.f, t0 = 0.f, t1 = 0.f;
        #pragma unroll
        for (int nf = 0; nf < 8; nf++) {
            int col = (nf << 3) + (l4 << 1);
            float b0 = bias[n0w + col], b1 = bias[n0w + col + 1];
            c[mf][nf][0] += b0; c[mf][nf][1] += b1;
            c[mf][nf][2] += b0; c[mf][nf][3] += b1;
            s0 += c[mf][nf][0] + c[mf][nf][1];
            s1 += c[mf][nf][2] + c[mf][nf][3];
            t0 += c[mf][nf][0] * c[mf][nf][0] + c[mf][nf][1] * c[mf][nf][1];
            t1 += c[mf][nf][2] * c[mf][nf][2] + c[mf][nf][3] * c[mf][nf][3];
        }
        #pragma unroll
        for (int off = 1; off <= 2; off <<= 1) {
            s0 += __shfl_xor_sync(0xffffffffu, s0, off);
            s1 += __shfl_xor_sync(0xffffffffu, s1, off);
            t0 += __shfl_xor_sync(0xffffffffu, t0, off);
            t1 += __shfl_xor_sync(0xffffffffu, t1, off);
        }
        float mean0 = 0.f, mean1 = 0.f, inv0 = 1.f, inv1 = 1.f;
        if (do_ln) {
            mean0 = s0 * 0.015625f;
            mean1 = s1 * 0.015625f;
            inv0 = rsqrtf(t0 * 0.015625f - mean0 * mean0 + 1e-5f);
            inv1 = rsqrtf(t1 * 0.015625f - mean1 * mean1 + 1e-5f);
        }

        int r0 = (wm << 6) + (mf << 4) + grp;
        int m = m0 + r0;
        int b = m >> 11, nseq = m & 2047;
        size_t qkbase0 = (((size_t)(b * HH + head)) * NN + nseq) * DD;
        size_t qkbase1 = qkbase0 + (size_t)8 * DD;
        size_t vbase = ((size_t)(b * HH + head)) * ((size_t)64 * NN);
        int tp = (nseq & ~7) | sg;
        #pragma unroll
        for (int nf = 0; nf < 8; nf++) {
            int col = (nf << 3) + (l4 << 1);
            float y0 = c[mf][nf][0], y1 = c[mf][nf][1];
            float y2 = c[mf][nf][2], y3 = c[mf][nf][3];
            if (do_ln) {
                float g0 = gam[col], g1 = gam[col + 1];
                float e0 = bet[col], e1 = bet[col + 1];
                y0 = (y0 - mean0) * inv0 * g0 + e0;
                y1 = (y1 - mean0) * inv0 * g1 + e1;
                y2 = (y2 - mean1) * inv1 * g0 + e0;
                y3 = (y3 - mean1) * inv1 * g1 + e1;
            }
            if (is_q) { y0 *= SC; y1 *= SC; y2 *= SC; y3 *= SC; }
            if (!is_v) {
                int gb = nf << 3;
                Out[qkbase0 + gb + p0] = f2tf(y0);
                Out[qkbase0 + gb + p1] = f2tf(y1);
                Out[qkbase1 + gb + p0] = f2tf(y2);
                Out[qkbase1 + gb + p1] = f2tf(y3);
            } else {
                Out[vbase + (size_t)col * NN + tp]           = f2tf(y0);
                Out[vbase + (size_t)(col + 1) * NN + tp]     = f2tf(y1);
                Out[vbase + (size_t)col * NN + tp + 8]       = f2tf(y2);
                Out[vbase + (size_t)(col + 1) * NN + tp + 8] = f2tf(y3);
            }
        }
    }
}

// ---------------------------------------------------------------------------
// Flash attention (tf32 MMA), unnormalized exp2 accumulation. All fragment
// operand pairs are adjacent in smem (sigma-permuted layouts) -> LDS.64.
// Key-permuted K rows make the S-fragment directly the PV A-fragment.
// exp2 of groups 4-7 interleaved with PV of groups 0-3. K/V double-buffered.
// 108 KB smem -> 2 CTAs/SM.
// ---------------------------------------------------------------------------
#define QS_F (128*72)
#define KS_F (64*72)
#define VS_F (64*72)
#define ATTN_SMEM ((QS_F + 2*KS_F + 2*VS_F) * 4)   // 110592 bytes

__global__ __launch_bounds__(128, 2) void attn_kernel(float* __restrict__ out)
{
    extern __shared__ float sm[];
    float* Qs  = sm;                       // [128][72] (d sigma-permuted)
    float* Ksb = sm + QS_F;                // 2 x [64 keys(perm)][72 d(perm)]
    float* Vsb = sm + QS_F + 2 * KS_F;     // 2 x [64 d][72 keys(perm)]

    int tid = threadIdx.x;
    int wid = tid >> 5, lane = tid & 31;
    int grp = lane >> 2, l4 = lane & 3;
    int bh = blockIdx.y, qt = blockIdx.x;
    int mb = wid << 5;

    const float* qb  = g_q + (size_t)bh * (NN * 64) + (size_t)qt * (128 * 64);
    const float* kb  = g_k + (size_t)bh * (NN * 64);
    const float* vtb = g_v + (size_t)bh * (NN * 64);   // [64 d][2048 tokens]

    uint32_t qs_u = smem_u32(Qs), ks_u = smem_u32(Ksb), vs_u = smem_u32(Vsb);
    int lr = tid >> 4, lch = tid & 15;
    int slr = ((lr & 3) << 1) | (lr >> 2);   // key permutation within 8-group

    // prologue: Q + K0/V0 (group A), then K1/V1 (group B)
    #pragma unroll
    for (int i = 0; i < 8; i++) {
        int r = lr + (i << 3);
        cp16(qs_u + r * 288 + (lch << 4), qb + r * 64 + (lch << 2));
        cp16(qs_u + (r + 64) * 288 + (lch << 4), qb + (r + 64) * 64 + (lch << 2));
        cp16(ks_u + ((i << 3) + slr) * 288 + (lch << 4), kb + r * 64 + (lch << 2));
        cp16(vs_u + r * 288 + (lch << 4), vtb + (size_t)r * NN + (lch << 2));
    }
    cp_commit();
    #pragma unroll
    for (int i = 0; i < 8; i++) {
        int r = lr + (i << 3);
        cp16(ks_u + KS_F * 4 + ((i << 3) + slr) * 288 + (lch << 4),
             kb + 4096 + r * 64 + (lch << 2));
        cp16(vs_u + VS_F * 4 + r * 288 + (lch << 4),
             vtb + (size_t)r * NN + 64 + (lch << 2));
    }
    cp_commit();
    cp_wait1();        // group A complete
    __syncthreads();

    float o[2][8][4];
    #pragma unroll
    for (int mf = 0; mf < 2; mf++)
        #pragma unroll
        for (int df = 0; df < 8; df++)
            #pragma unroll
            for (int i = 0; i < 4; i++) o[mf][df][i] = 0.f;
    float l_i[4] = {0.f, 0.f, 0.f, 0.f};

    for (int kt = 0; kt < 32; kt++) {
        int buf = kt & 1;
        const float* Ks = Ksb + buf * KS_F;
        const float* Vs = Vsb + buf * VS_F;

        // S = Q @ K^T (log2 domain)
        float s[2][8][4];
        #pragma unroll
        for (int mf = 0; mf < 2; mf++)
            #pragma unroll
            for (int nf = 0; nf < 8; nf++)
                #pragma unroll
                for (int i = 0; i < 4; i++) s[mf][nf][i] = 0.f;

        #pragma unroll
        for (int ks8 = 0; ks8 < 8; ks8++) {
            int k8 = (ks8 << 3) + (l4 << 1);
            uint32_t a[2][4], b[8][2];
            #pragma unroll
            for (int mf = 0; mf < 2; mf++) {
                int r = mb + (mf << 4) + grp;
                uint2 qa = *(const uint2*)&Qs[r * 72 + k8];
                uint2 qc = *(const uint2*)&Qs[(r + 8) * 72 + k8];
                a[mf][0] = qa.x; a[mf][1] = qc.x; a[mf][2] = qa.y; a[mf][3] = qc.y;
            }
            #pragma unroll
            for (int nf = 0; nf < 8; nf++) {
                int n = (nf << 3) + grp;
                uint2 kv = *(const uint2*)&Ks[n * 72 + k8];
                b[nf][0] = kv.x; b[nf][1] = kv.y;
            }
            #pragma unroll
            for (int mf = 0; mf < 2; mf++)
                #pragma unroll
                for (int nf = 0; nf < 8; nf++)
                    mma8(s[mf][nf], a[mf], b[nf]);
        }

        // exp2 groups 0..3
        #pragma unroll
        for (int g = 0; g < 4; g++)
            #pragma unroll
            for (int mf = 0; mf < 2; mf++) {
                float v0 = ex2(s[mf][g][0]); float v1 = ex2(s[mf][g][1]);
                float v2 = ex2(s[mf][g][2]); float v3 = ex2(s[mf][g][3]);
                s[mf][g][0] = v0; s[mf][g][1] = v1; s[mf][g][2] = v2; s[mf][g][3] = v3;
                l_i[mf << 1] += v0 + v1; l_i[(mf << 1) + 1] += v2 + v3;
            }

        // PV groups 0..3, interleaved with exp2 of groups 4..7
        #pragma unroll
        for (int g = 0; g < 4; g++) {
            #pragma unroll
            for (int mf = 0; mf < 2; mf++) {
                float v0 = ex2(s[mf][g + 4][0]); float v1 = ex2(s[mf][g + 4][1]);
                float v2 = ex2(s[mf][g + 4][2]); float v3 = ex2(s[mf][g + 4][3]);
                s[mf][g + 4][0] = v0; s[mf][g + 4][1] = v1;
                s[mf][g + 4][2] = v2; s[mf][g + 4][3] = v3;
                l_i[mf << 1] += v0 + v1; l_i[(mf << 1) + 1] += v2 + v3;
            }
            int kc = (g << 3) + (l4 << 1);
            uint32_t b[8][2];
            #pragma unroll
            for (int df = 0; df < 8; df++) {
                int n = (df << 3) + grp;
                uint2 vv = *(const uint2*)&Vs[n * 72 + kc];
                b[df][0] = vv.x; b[df][1] = vv.y;
            }
            #pragma unroll
            for (int mf = 0; mf < 2; mf++) {
                uint32_t a[4];
                a[0] = __float_as_uint(s[mf][g][0]);
                a[1] = __float_as_uint(s[mf][g][2]);
                a[2] = __float_as_uint(s[mf][g][1]);
                a[3] = __float_as_uint(s[mf][g][3]);
                #pragma unroll
                for (int df = 0; df < 8; df++)
                    mma8(o[mf][df], a, b[df]);
            }
        }
        // PV groups 4..7
        #pragma unroll
        for (int g = 4; g < 8; g++) {
            int kc = (g << 3) + (l4 << 1);
            uint32_t b[8][2];
            #pragma unroll
            for (int df = 0; df < 8; df++) {
                int n = (df << 3) + grp;
                uint2 vv = *(const uint2*)&Vs[n * 72 + kc];
                b[df][0] = vv.x; b[df][1] = vv.y;
            }
            #pragma unroll
            for (int mf = 0; mf < 2; mf++) {
                uint32_t a[4];
                a[0] = __float_as_uint(s[mf][g][0]);
                a[1] = __float_as_uint(s[mf][g][2]);
                a[2] = __float_as_uint(s[mf][g][1]);
                a[3] = __float_as_uint(s[mf][g][3]);
                #pragma unroll
                for (int df = 0; df < 8; df++)
                    mma8(o[mf][df], a, b[df]);
            }
        }

        if (kt < 31) {
            __syncthreads();       // all warps done with buf
            if (kt < 30) {
                const float* kn = kb + (kt + 2) * 4096;
                uint32_t kdst = ks_u + buf * (KS_F * 4);
                uint32_t vdst = vs_u + buf * (VS_F * 4);
                int koff = (kt + 2) * 64;
                #pragma unroll
                for (int i = 0; i < 8; i++) {
                    int r = lr + (i << 3);
                    cp16(kdst + ((i << 3) + slr) * 288 + (lch << 4),
                         kn + r * 64 + (lch << 2));
                    cp16(vdst + r * 288 + (lch << 4),
                         vtb + (size_t)r * NN + koff + (lch << 2));
                }
                cp_commit();
                cp_wait1();
            } else {
                cp_wait0();
            }
            __syncthreads();
        }
    }

    // epilogue: reduce row sums across quad, normalize, write out[b][n][h*64+d]
    #pragma unroll
    for (int si = 0; si < 4; si++) {
        l_i[si] += __shfl_xor_sync(0xffffffffu, l_i[si], 1);
        l_i[si] += __shfl_xor_sync(0xffffffffu, l_i[si], 2);
    }
    int b = bh >> 4, h = bh & 15;
    #pragma unroll
    for (int mf = 0; mf < 2; mf++) {
        #pragma unroll
        for (int rr = 0; rr < 2; rr++) {
            int si = (mf << 1) + rr;
            float inv = 1.f / l_i[si];
            int n = (qt << 7) + mb + (mf << 4) + grp + (rr << 3);
            size_t base = ((size_t)(b * NN + n)) * CC + (h << 6);
            #pragma unroll
            for (int df = 0; df < 8; df++) {
                int col = (df << 3) + (l4 << 1);
                float2 vo = make_float2(o[mf][df][rr * 2] * inv,
                                        o[mf][df][rr * 2 + 1] * inv);
                *(float2*)&out[base + col] = vo;
            }
        }
    }
}

// ---------------------------------------------------------------------------
extern "C" void kernel_launch(void* const* d_in, const int* in_sizes, int n_in,
                              void* d_out, int out_size)
{
    const float* x1   = (const float*)d_in[0];
    const float* x2   = (const float*)d_in[1];
    const float* wq   = (const float*)d_in[2];
    const float* bq   = (const float*)d_in[3];
    const float* wkv  = (const float*)d_in[4];
    const float* bkv  = (const float*)d_in[5];
    const float* gmq  = (const float*)d_in[6];
    const float* btq  = (const float*)d_in[7];
    const float* gmk  = (const float*)d_in[8];
    const float* btk  = (const float*)d_in[9];
    float* out = (float*)d_out;

    cudaFuncSetAttribute(attn_kernel, cudaFuncAttributeMaxDynamicSharedMemorySize, ATTN_SMEM);
    cudaFuncSetAttribute(proj_kernel, cudaFuncAttributeMaxDynamicSharedMemorySize, PROJ_SMEM);

    float *dx1t, *dx2t, *dwqt, *dwkvt;
    cudaGetSymbolAddress((void**)&dx1t, g_x1t);
    cudaGetSymbolAddress((void**)&dx2t, g_x2t);
    cudaGetSymbolAddress((void**)&dwqt, g_wqt);
    cudaGetSymbolAddress((void**)&dwkvt, g_wkvt);

    prep_kernel<<<(MM * CC / 4) / 256, 256>>>(x1, dx1t, MM * CC / 4);
    prep_kernel<<<(MM * CC / 4) / 256, 256>>>(x2, dx2t, MM * CC / 4);
    prep_kernel<<<(CC * CC / 4) / 256, 256>>>(wq, dwqt, CC * CC / 4);
    prep_kernel<<<(CC * 2 * CC / 4) / 256, 256>>>(wkv, dwkvt, CC * 2 * CC / 4);

    proj_kernel<<<dim3(24, MM / 128), 128, PROJ_SMEM>>>(bq, bkv, gmq, btq, gmk, btk);

    attn_kernel<<<dim3(NN / 128, BB * HH), 128, ATTN_SMEM>>>(out);
}

// round 11
// speedup vs baseline: 1.5291x; 1.5291x over previous
#include <cuda_runtime.h>
#include <cstdint>

#define BB 4
#define NN 2048
#define CC 1024
#define HH 16
#define DD 64
#define MM (BB*NN)          // 8192

// Scratch (tf32-rounded; q,k post-LN; q pre-scaled by 0.125*log2e):
//   g_q, g_k : [bh][token][64 d], d-columns sigma-permuted within 8-groups
//   g_v      : [bh][token][64 d], natural layout
__device__ float g_q[(size_t)MM * CC];
__device__ float g_k[(size_t)MM * CC];
__device__ float g_v[(size_t)MM * CC];
// tf32-pre-rounded copies of inputs
__device__ float g_x1t[(size_t)MM * CC];
__device__ float g_x2t[(size_t)MM * CC];
__device__ float g_wqt[(size_t)CC * CC];
__device__ float g_wkvt[(size_t)CC * 2 * CC];

// ---------------------------------------------------------------------------
// helpers
// ---------------------------------------------------------------------------
__device__ __forceinline__ float f2tf(float x) {
    uint32_t u;
    asm("cvt.rna.tf32.f32 %0, %1;" : "=r"(u) : "f"(x));
    return __uint_as_float(u);
}

__device__ __forceinline__ float ex2(float x) {
    float r;
    asm("ex2.approx.ftz.f32 %0, %1;" : "=f"(r) : "f"(x));
    return r;
}

__device__ __forceinline__ uint32_t smem_u32(const void* p) {
    uint32_t a;
    asm("{ .reg .u64 t; cvta.to.shared.u64 t, %1; cvt.u32.u64 %0, t; }" : "=r"(a) : "l"(p));
    return a;
}

__device__ __forceinline__ void cp16(uint32_t dst, const void* src) {
    asm volatile("cp.async.cg.shared.global [%0], [%1], 16;" :: "r"(dst), "l"(src));
}
__device__ __forceinline__ void cp_commit() { asm volatile("cp.async.commit_group;"); }
__device__ __forceinline__ void cp_wait0()  { asm volatile("cp.async.wait_group 0;"); }
__device__ __forceinline__ void cp_wait1()  { asm volatile("cp.async.wait_group 1;"); }

__device__ __forceinline__ void mma8(float c[4], const uint32_t a[4], const uint32_t b[2]) {
    asm volatile(
        "mma.sync.aligned.m16n8k8.row.col.f32.tf32.tf32.f32 "
        "{%0,%1,%2,%3}, {%4,%5,%6,%7}, {%8,%9}, {%0,%1,%2,%3};\n"
        : "+f"(c[0]), "+f"(c[1]), "+f"(c[2]), "+f"(c[3])
        : "r"(a[0]), "r"(a[1]), "r"(a[2]), "r"(a[3]), "r"(b[0]), "r"(b[1]));
}

// ---------------------------------------------------------------------------
// Elementwise tf32 pre-rounding pass
// ---------------------------------------------------------------------------
__global__ __launch_bounds__(256) void prep_kernel(const float* __restrict__ src,
                                                   float* __restrict__ dst, int n4)
{
    int i = blockIdx.x * 256 + threadIdx.x;
    if (i < n4) {
        float4 v = ((const float4*)src)[i];
        ((float4*)dst)[i] = make_float4(f2tf(v.x), f2tf(v.y), f2tf(v.z), f2tf(v.w));
    }
}

// ---------------------------------------------------------------------------
// Projection GEMM (q + kv in one launch), tf32 MMA, cp.async double-buffered.
// Block tile 128x128 (2 heads); 4 warps, each 64x64.
// Epilogue: bias + per-head LN (q,k), q log2-scale; q/k stored with sigma-
// permuted d-columns (same 32B sectors, scalar stores); v natural float2.
// ---------------------------------------------------------------------------
#define PROJ_SMEM ((2*128*36 + 2*32*136) * 4)   // 71680 bytes

__global__ __launch_bounds__(128, 3) void proj_kernel(
    const float* __restrict__ bq, const float* __restrict__ bkv,
    const float* __restrict__ gamq, const float* __restrict__ betq,
    const float* __restrict__ gamk, const float* __restrict__ betk)
{
    extern __shared__ float psm[];
    float (*As)[36]  = (float(*)[36])psm;
    float (*Bs)[136] = (float(*)[136])(psm + 2 * 128 * 36);

    int tid  = threadIdx.x;
    int wid  = tid >> 5, lane = tid & 31;
    int grp  = lane >> 2, l4 = lane & 3;
    int wm   = wid >> 1, wn = wid & 1;
    int m0   = blockIdx.y << 7;
    int cb   = blockIdx.x;            // 0..23

    const float *A, *W, *bias, *gam, *bet;
    float* Out; int ld, n0, do_ln, is_q, is_v;
    if (cb < 8) {
        A = g_x1t; W = g_wqt; bias = bq; ld = CC; n0 = cb << 7;
        Out = g_q; do_ln = 1; is_q = 1; is_v = 0; gam = gamq; bet = betq;
    } else {
        int c2 = cb - 8;
        A = g_x2t; W = g_wkvt; bias = bkv; ld = 2 * CC; n0 = c2 << 7; is_q = 0;
        if (c2 < 8) { Out = g_k; do_ln = 1; is_v = 0; gam = gamk; bet = betk; }
        else        { Out = g_v; do_ln = 0; is_v = 1; gam = gamq; bet = betq; }
    }
    int n0w = n0 + (wn << 6);
    int head = (is_v ? (n0w - 1024) : n0w) >> 6;

    float c[4][8][4];
    #pragma unroll
    for (int mf = 0; mf < 4; mf++)
        #pragma unroll
        for (int nf = 0; nf < 8; nf++)
            #pragma unroll
            for (int i = 0; i < 4; i++) c[mf][nf][i] = 0.f;

    uint32_t as_u = smem_u32(As), bs_u = smem_u32(Bs);
    int ar = tid >> 3, ac = tid & 7;
    int br = tid >> 5, bc = tid & 31;
    const float* Ap = A + (size_t)(m0 + ar) * CC + (ac << 2);
    const float* Wp = W + (size_t)br * ld + n0 + (bc << 2);

    #pragma unroll
    for (int i = 0; i < 8; i++) {
        cp16(as_u + ((ar + (i << 4)) * 36 + (ac << 2)) * 4, Ap + (size_t)(i << 4) * CC);
        cp16(bs_u + ((br + (i << 2)) * 136 + (bc << 2)) * 4, Wp + (size_t)(i << 2) * ld);
    }
    cp_commit();

    for (int ch = 0; ch < 32; ch++) {
        int buf = ch & 1;
        if (ch < 31) {
            int k0 = (ch + 1) << 5;
            int ob = buf ^ 1;
            #pragma unroll
            for (int i = 0; i < 8; i++) {
                cp16(as_u + (((ob << 7) + ar + (i << 4)) * 36 + (ac << 2)) * 4,
                     Ap + (size_t)(i << 4) * CC + k0);
                cp16(bs_u + (((ob << 5) + br + (i << 2)) * 136 + (bc << 2)) * 4,
                     Wp + (size_t)(k0 + (i << 2)) * ld);
            }
            cp_commit();
            cp_wait1();
        } else {
            cp_wait0();
        }
        __syncthreads();

        float (*Ab)[36]  = &As[buf << 7];
        float (*Bb)[136] = &Bs[buf << 5];
        #pragma unroll
        for (int ks = 0; ks < 4; ks++) {
            int k8 = ks << 3;
            uint32_t a[4][4];
            #pragma unroll
            for (int mf = 0; mf < 4; mf++) {
                int r = (wm << 6) + (mf << 4) + grp;
                a[mf][0] = __float_as_uint(Ab[r][k8 + l4]);
                a[mf][1] = __float_as_uint(Ab[r + 8][k8 + l4]);
                a[mf][2] = __float_as_uint(Ab[r][k8 + l4 + 4]);
                a[mf][3] = __float_as_uint(Ab[r + 8][k8 + l4 + 4]);
            }
            #pragma unroll
            for (int nf = 0; nf < 8; nf++) {
                int n = (wn << 6) + (nf << 3) + grp;
                uint32_t b[2];
                b[0] = __float_as_uint(Bb[k8 + l4][n]);
                b[1] = __float_as_uint(Bb[k8 + l4 + 4][n]);
                #pragma unroll
                for (int mf = 0; mf < 4; mf++)
                    mma8(c[mf][nf], a[mf], b);
            }
        }
        __syncthreads();
    }

    // Epilogue
    const float SC = 0.18033688011112042f;     // 0.125 * log2(e)
    // sigma positions for logical cols (2*l4, 2*l4+1) within each 8-group
    int p0 = (((l4 << 1) & 3) << 1) | (l4 >> 1);        // {0,4,1,5}
    int p1 = ((((l4 << 1) + 1) & 3) << 1) | (l4 >> 1);  // {2,6,3,7}

    #pragma unroll
    for (int mf = 0; mf < 4; mf++) {
        float s0 = 0.f, s1 = 0.f, t0 = 0.f, t1 = 0.f;
        #pragma unroll
        for (int nf = 0; nf < 8; nf++) {
            int col = (nf << 3) + (l4 << 1);
            float b0 = bias[n0w + col], b1 = bias[n0w + col + 1];
            c[mf][nf][0] += b0; c[mf][nf][1] += b1;
            c[mf][nf][2] += b0; c[mf][nf][3] += b1;
            s0 += c[mf][nf][0] + c[mf][nf][1];
            s1 += c[mf][nf][2] + c[mf][nf][3];
            t0 += c[mf][nf][0] * c[mf][nf][0] + c[mf][nf][1] * c[mf][nf][1];
            t1 += c[mf][nf][2] * c[mf][nf][2] + c[mf][nf][3] * c[mf][nf][3];
        }
        #pragma unroll
        for (int off = 1; off <= 2; off <<= 1) {
            s0 += __shfl_xor_sync(0xffffffffu, s0, off);
            s1 += __shfl_xor_sync(0xffffffffu, s1, off);
            t0 += __shfl_xor_sync(0xffffffffu, t0, off);
            t1 += __shfl_xor_sync(0xffffffffu, t1, off);
        }
        float mean0 = 0.f, mean1 = 0.f, inv0 = 1.f, inv1 = 1.f;
        if (do_ln) {
            mean0 = s0 * 0.015625f;
            mean1 = s1 * 0.015625f;
            inv0 = rsqrtf(t0 * 0.015625f - mean0 * mean0 + 1e-5f);
            inv1 = rsqrtf(t1 * 0.015625f - mean1 * mean1 + 1e-5f);
        }

        int r0 = (wm << 6) + (mf << 4) + grp;
        int m = m0 + r0;
        int b = m >> 11, nseq = m & 2047;
        size_t base0 = (((size_t)(b * HH + head)) * NN + nseq) * DD;
        size_t base1 = base0 + (size_t)8 * DD;
        #pragma unroll
        for (int nf = 0; nf < 8; nf++) {
            int col = (nf << 3) + (l4 << 1);
            float y0 = c[mf][nf][0], y1 = c[mf][nf][1];
            float y2 = c[mf][nf][2], y3 = c[mf][nf][3];
            if (do_ln) {
                float g0 = gam[col], g1 = gam[col + 1];
                float e0 = bet[col], e1 = bet[col + 1];
                y0 = (y0 - mean0) * inv0 * g0 + e0;
                y1 = (y1 - mean0) * inv0 * g1 + e1;
                y2 = (y2 - mean1) * inv1 * g0 + e0;
                y3 = (y3 - mean1) * inv1 * g1 + e1;
            }
            if (is_q) { y0 *= SC; y1 *= SC; y2 *= SC; y3 *= SC; }
            if (!is_v) {
                int gb = nf << 3;   // sigma-permuted scalar stores (same 32B sectors)
                Out[base0 + gb + p0] = f2tf(y0);
                Out[base0 + gb + p1] = f2tf(y1);
                Out[base1 + gb + p0] = f2tf(y2);
                Out[base1 + gb + p1] = f2tf(y3);
            } else {
                *(float2*)&Out[base0 + col] = make_float2(f2tf(y0), f2tf(y1));
                *(float2*)&Out[base1 + col] = make_float2(f2tf(y2), f2tf(y3));
            }
        }
    }
}

// ---------------------------------------------------------------------------
// Flash attention (tf32 MMA), unnormalized exp2 accumulation.
// Q/K: sigma-permuted d-columns -> uint2 fragment loads (conflict-free).
// K rows key-permuted ([0,4,1,5,2,6,3,7]) -> S-fragment IS the PV A-fragment.
// V: natural [token][d], 32-bit fragment loads. K/V double-buffered.
// exp2 of groups 4-7 interleaved with PV of groups 0-3. 108 KB smem, 2 CTAs/SM.
// ---------------------------------------------------------------------------
#define QS_F (128*72)
#define KS_F (64*72)
#define VS_F (64*72)
#define ATTN_SMEM ((QS_F + 2*KS_F + 2*VS_F) * 4)   // 110592 bytes

__global__ __launch_bounds__(128, 2) void attn_kernel(float* __restrict__ out)
{
    extern __shared__ float sm[];
    float* Qs  = sm;                       // [128][72] (d sigma-permuted)
    float* Ksb = sm + QS_F;                // 2 x [64 keys(perm)][72 d(perm)]
    float* Vsb = sm + QS_F + 2 * KS_F;     // 2 x [64 tokens][72 d]

    int tid = threadIdx.x;
    int wid = tid >> 5, lane = tid & 31;
    int grp = lane >> 2, l4 = lane & 3;
    int bh = blockIdx.y, qt = blockIdx.x;
    int mb = wid << 5;

    const float* qb = g_q + (size_t)bh * (NN * 64) + (size_t)qt * (128 * 64);
    const float* kb = g_k + (size_t)bh * (NN * 64);
    const float* vb = g_v + (size_t)bh * (NN * 64);

    uint32_t qs_u = smem_u32(Qs), ks_u = smem_u32(Ksb), vs_u = smem_u32(Vsb);
    int lr = tid >> 4, lch = tid & 15;
    int slr = ((lr & 3) << 1) | (lr >> 2);   // key permutation within 8-group

    // prologue: Q + K0/V0 (group A), then K1/V1 (group B)
    #pragma unroll
    for (int i = 0; i < 8; i++) {
        int r = lr + (i << 3);
        cp16(qs_u + r * 288 + (lch << 4), qb + r * 64 + (lch << 2));
        cp16(qs_u + (r + 64) * 288 + (lch << 4), qb + (r + 64) * 64 + (lch << 2));
        cp16(ks_u + ((i << 3) + slr) * 288 + (lch << 4), kb + r * 64 + (lch << 2));
        cp16(vs_u + r * 288 + (lch << 4), vb + r * 64 + (lch << 2));
    }
    cp_commit();
    #pragma unroll
    for (int i = 0; i < 8; i++) {
        int r = lr + (i << 3);
        cp16(ks_u + KS_F * 4 + ((i << 3) + slr) * 288 + (lch << 4),
             kb + 4096 + r * 64 + (lch << 2));
        cp16(vs_u + VS_F * 4 + r * 288 + (lch << 4),
             vb + 4096 + r * 64 + (lch << 2));
    }
    cp_commit();
    cp_wait1();        // group A complete
    __syncthreads();

    float o[2][8][4];
    #pragma unroll
    for (int mf = 0; mf < 2; mf++)
        #pragma unroll
        for (int df = 0; df < 8; df++)
            #pragma unroll
            for (int i = 0; i < 4; i++) o[mf][df][i] = 0.f;
    float l_i[4] = {0.f, 0.f, 0.f, 0.f};

    for (int kt = 0; kt < 32; kt++) {
        int buf = kt & 1;
        const float* Ks = Ksb + buf * KS_F;
        const float* Vs = Vsb + buf * VS_F;

        // S = Q @ K^T (log2 domain), uint2 fragment loads
        float s[2][8][4];
        #pragma unroll
        for (int mf = 0; mf < 2; mf++)
            #pragma unroll
            for (int nf = 0; nf < 8; nf++)
                #pragma unroll
                for (int i = 0; i < 4; i++) s[mf][nf][i] = 0.f;

        #pragma unroll
        for (int ks8 = 0; ks8 < 8; ks8++) {
            int k8 = (ks8 << 3) + (l4 << 1);
            uint32_t a[2][4], b[8][2];
            #pragma unroll
            for (int mf = 0; mf < 2; mf++) {
                int r = mb + (mf << 4) + grp;
                uint2 qa = *(const uint2*)&Qs[r * 72 + k8];
                uint2 qc = *(const uint2*)&Qs[(r + 8) * 72 + k8];
                a[mf][0] = qa.x; a[mf][1] = qc.x; a[mf][2] = qa.y; a[mf][3] = qc.y;
            }
            #pragma unroll
            for (int nf = 0; nf < 8; nf++) {
                int n = (nf << 3) + grp;
                uint2 kv = *(const uint2*)&Ks[n * 72 + k8];
                b[nf][0] = kv.x; b[nf][1] = kv.y;
            }
            #pragma unroll
            for (int mf = 0; mf < 2; mf++)
                #pragma unroll
                for (int nf = 0; nf < 8; nf++)
                    mma8(s[mf][nf], a[mf], b[nf]);
        }

        // exp2 groups 0..3
        #pragma unroll
        for (int g = 0; g < 4; g++)
            #pragma unroll
            for (int mf = 0; mf < 2; mf++) {
                float v0 = ex2(s[mf][g][0]); float v1 = ex2(s[mf][g][1]);
                float v2 = ex2(s[mf][g][2]); float v3 = ex2(s[mf][g][3]);
                s[mf][g][0] = v0; s[mf][g][1] = v1; s[mf][g][2] = v2; s[mf][g][3] = v3;
                l_i[mf << 1] += v0 + v1; l_i[(mf << 1) + 1] += v2 + v3;
            }

        // PV groups 0..3, interleaved with exp2 of groups 4..7
        #pragma unroll
        for (int g = 0; g < 4; g++) {
            #pragma unroll
            for (int mf = 0; mf < 2; mf++) {
                float v0 = ex2(s[mf][g + 4][0]); float v1 = ex2(s[mf][g + 4][1]);
                float v2 = ex2(s[mf][g + 4][2]); float v3 = ex2(s[mf][g + 4][3]);
                s[mf][g + 4][0] = v0; s[mf][g + 4][1] = v1;
                s[mf][g + 4][2] = v2; s[mf][g + 4][3] = v3;
                l_i[mf << 1] += v0 + v1; l_i[(mf << 1) + 1] += v2 + v3;
            }
            int k8 = g << 3;
            uint32_t b[8][2];
            #pragma unroll
            for (int df = 0; df < 8; df++) {
                int n = (df << 3) + grp;
                b[df][0] = __float_as_uint(Vs[(k8 + l4) * 72 + n]);
                b[df][1] = __float_as_uint(Vs[(k8 + l4 + 4) * 72 + n]);
            }
            #pragma unroll
            for (int mf = 0; mf < 2; mf++) {
                uint32_t a[4];
                a[0] = __float_as_uint(s[mf][g][0]);
                a[1] = __float_as_uint(s[mf][g][2]);
                a[2] = __float_as_uint(s[mf][g][1]);
                a[3] = __float_as_uint(s[mf][g][3]);
                #pragma unroll
                for (int df = 0; df < 8; df++)
                    mma8(o[mf][df], a, b[df]);
            }
        }
        // PV groups 4..7
        #pragma unroll
        for (int g = 4; g < 8; g++) {
            int k8 = g << 3;
            uint32_t b[8][2];
            #pragma unroll
            for (int df = 0; df < 8; df++) {
                int n = (df << 3) + grp;
                b[df][0] = __float_as_uint(Vs[(k8 + l4) * 72 + n]);
                b[df][1] = __float_as_uint(Vs[(k8 + l4 + 4) * 72 + n]);
            }
            #pragma unroll
            for (int mf = 0; mf < 2; mf++) {
                uint32_t a[4];
                a[0] = __float_as_uint(s[mf][g][0]);
                a[1] = __float_as_uint(s[mf][g][2]);
                a[2] = __float_as_uint(s[mf][g][1]);
                a[3] = __float_as_uint(s[mf][g][3]);
                #pragma unroll
                for (int df = 0; df < 8; df++)
                    mma8(o[mf][df], a, b[df]);
            }
        }

        if (kt < 31) {
            __syncthreads();       // all warps done with buf
            if (kt < 30) {
                const float* kn = kb + (kt + 2) * 4096;
                const float* vn = vb + (kt + 2) * 4096;
                uint32_t kdst = ks_u + buf * (KS_F * 4);
                uint32_t vdst = vs_u + buf * (VS_F * 4);
                #pragma unroll
                for (int i = 0; i < 8; i++) {
                    int r = lr + (i << 3);
                    cp16(kdst + ((i << 3) + slr) * 288 + (lch << 4),
                         kn + r * 64 + (lch << 2));
                    cp16(vdst + r * 288 + (lch << 4), vn + r * 64 + (lch << 2));
                }
                cp_commit();
                cp_wait1();
            } else {
                cp_wait0();
            }
            __syncthreads();
        }
    }

    // epilogue: reduce row sums across quad, normalize, write out[b][n][h*64+d]
    #pragma unroll
    for (int si = 0; si < 4; si++) {
        l_i[si] += __shfl_xor_sync(0xffffffffu, l_i[si], 1);
        l_i[si] += __shfl_xor_sync(0xffffffffu, l_i[si], 2);
    }
    int b = bh >> 4, h = bh & 15;
    #pragma unroll
    for (int mf = 0; mf < 2; mf++) {
        #pragma unroll
        for (int rr = 0; rr < 2; rr++) {
            int si = (mf << 1) + rr;
            float inv = 1.f / l_i[si];
            int n = (qt << 7) + mb + (mf << 4) + grp + (rr << 3);
            size_t base = ((size_t)(b * NN + n)) * CC + (h << 6);
            #pragma unroll
            for (int df = 0; df < 8; df++) {
                int col = (df << 3) + (l4 << 1);
                float2 vo = make_float2(o[mf][df][rr * 2] * inv,
                                        o[mf][df][rr * 2 + 1] * inv);
                *(float2*)&out[base + col] = vo;
            }
        }
    }
}

// ---------------------------------------------------------------------------
extern "C" void kernel_launch(void* const* d_in, const int* in_sizes, int n_in,
                              void* d_out, int out_size)
{
    const float* x1   = (const float*)d_in[0];
    const float* x2   = (const float*)d_in[1];
    const float* wq   = (const float*)d_in[2];
    const float* bq   = (const float*)d_in[3];
    const float* wkv  = (const float*)d_in[4];
    const float* bkv  = (const float*)d_in[5];
    const float* gmq  = (const float*)d_in[6];
    const float* btq  = (const float*)d_in[7];
    const float* gmk  = (const float*)d_in[8];
    const float* btk  = (const float*)d_in[9];
    float* out = (float*)d_out;

    cudaFuncSetAttribute(attn_kernel, cudaFuncAttributeMaxDynamicSharedMemorySize, ATTN_SMEM);
    cudaFuncSetAttribute(proj_kernel, cudaFuncAttributeMaxDynamicSharedMemorySize, PROJ_SMEM);

    float *dx1t, *dx2t, *dwqt, *dwkvt;
    cudaGetSymbolAddress((void**)&dx1t, g_x1t);
    cudaGetSymbolAddress((void**)&dx2t, g_x2t);
    cudaGetSymbolAddress((void**)&dwqt, g_wqt);
    cudaGetSymbolAddress((void**)&dwkvt, g_wkvt);

    prep_kernel<<<(MM * CC / 4) / 256, 256>>>(x1, dx1t, MM * CC / 4);
    prep_kernel<<<(MM * CC / 4) / 256, 256>>>(x2, dx2t, MM * CC / 4);
    prep_kernel<<<(CC * CC / 4) / 256, 256>>>(wq, dwqt, CC * CC / 4);
    prep_kernel<<<(CC * 2 * CC / 4) / 256, 256>>>(wkv, dwkvt, CC * 2 * CC / 4);

    proj_kernel<<<dim3(24, MM / 128), 128, PROJ_SMEM>>>(bq, bkv, gmq, btq, gmk, btk);

    attn_kernel<<<dim3(NN / 128, BB * HH), 128, ATTN_SMEM>>>(out);
}

// round 13
// speedup vs baseline: 1.5929x; 1.0417x over previous
#include <cuda_runtime.h>
#include <cstdint>

#define BB 4
#define NN 2048
#define CC 1024
#define HH 16
#define DD 64
#define MM (BB*NN)          // 8192

// Scratch (tf32-rounded; q,k post-LN; q pre-scaled by 0.125*log2e); [bh][token][d]
__device__ float g_q[(size_t)MM * CC];
__device__ float g_k[(size_t)MM * CC];
__device__ float g_v[(size_t)MM * CC];
// tf32-pre-rounded copies of inputs
__device__ float g_x1t[(size_t)MM * CC];
__device__ float g_x2t[(size_t)MM * CC];
__device__ float g_wqt[(size_t)CC * CC];
__device__ float g_wkvt[(size_t)CC * 2 * CC];

// ---------------------------------------------------------------------------
// helpers
// ---------------------------------------------------------------------------
__device__ __forceinline__ float f2tf(float x) {
    uint32_t u;
    asm("cvt.rna.tf32.f32 %0, %1;" : "=r"(u) : "f"(x));
    return __uint_as_float(u);
}

__device__ __forceinline__ float ex2(float x) {
    float r;
    asm("ex2.approx.ftz.f32 %0, %1;" : "=f"(r) : "f"(x));
    return r;
}

__device__ __forceinline__ uint32_t smem_u32(const void* p) {
    uint32_t a;
    asm("{ .reg .u64 t; cvta.to.shared.u64 t, %1; cvt.u32.u64 %0, t; }" : "=r"(a) : "l"(p));
    return a;
}

__device__ __forceinline__ void cp16(uint32_t dst, const void* src) {
    asm volatile("cp.async.cg.shared.global [%0], [%1], 16;" :: "r"(dst), "l"(src));
}
__device__ __forceinline__ void cp_commit() { asm volatile("cp.async.commit_group;"); }
__device__ __forceinline__ void cp_wait0()  { asm volatile("cp.async.wait_group 0;"); }
__device__ __forceinline__ void cp_wait1()  { asm volatile("cp.async.wait_group 1;"); }

__device__ __forceinline__ void mma8(float c[4], const uint32_t a[4], const uint32_t b[2]) {
    asm volatile(
        "mma.sync.aligned.m16n8k8.row.col.f32.tf32.tf32.f32 "
        "{%0,%1,%2,%3}, {%4,%5,%6,%7}, {%8,%9}, {%0,%1,%2,%3};\n"
        : "+f"(c[0]), "+f"(c[1]), "+f"(c[2]), "+f"(c[3])
        : "r"(a[0]), "r"(a[1]), "r"(a[2]), "r"(a[3]), "r"(b[0]), "r"(b[1]));
}

// ---------------------------------------------------------------------------
// Merged elementwise tf32 pre-rounding pass (x1 | x2 | wq | wkv in one grid)
// block counts (float4 granularity / 256 threads):
//   x1: 8192, x2: 8192, wq: 1024, wkv: 2048  -> total 19456
// ---------------------------------------------------------------------------
__global__ __launch_bounds__(256) void prep_all(
    const float* __restrict__ x1, const float* __restrict__ x2,
    const float* __restrict__ wq, const float* __restrict__ wkv)
{
    int b = blockIdx.x;
    const float* src; float* dst; int off;
    if (b < 8192)       { src = x1;  dst = g_x1t;  off = b; }
    else if (b < 16384) { src = x2;  dst = g_x2t;  off = b - 8192; }
    else if (b < 17408) { src = wq;  dst = g_wqt;  off = b - 16384; }
    else                { src = wkv; dst = g_wkvt; off = b - 17408; }
    int i = off * 256 + threadIdx.x;
    float4 v = ((const float4*)src)[i];
    ((float4*)dst)[i] = make_float4(f2tf(v.x), f2tf(v.y), f2tf(v.z), f2tf(v.w));
}

// ---------------------------------------------------------------------------
// Projection GEMM (q + kv in one launch), tf32 MMA.
// 3-stage cp.async pipeline: ONE barrier + one wait per 32-k chunk.
// Block tile 128x128 (2 heads); 4 warps, each 64x64.
// Epilogue: bias + per-head LN (q,k), q log2-scale, tf32 float2 stores.
// ---------------------------------------------------------------------------
#define PROJ_SMEM ((3*128*36 + 3*32*136) * 4)   // 107520 bytes

__global__ __launch_bounds__(128, 2) void proj_kernel(
    const float* __restrict__ bq, const float* __restrict__ bkv,
    const float* __restrict__ gamq, const float* __restrict__ betq,
    const float* __restrict__ gamk, const float* __restrict__ betk)
{
    extern __shared__ float psm[];
    float (*As)[36]  = (float(*)[36])psm;                   // [3*128][36]
    float (*Bs)[136] = (float(*)[136])(psm + 3 * 128 * 36); // [3*32][136]

    int tid  = threadIdx.x;
    int wid  = tid >> 5, lane = tid & 31;
    int grp  = lane >> 2, l4 = lane & 3;
    int wm   = wid >> 1, wn = wid & 1;
    int m0   = blockIdx.y << 7;
    int cb   = blockIdx.x;            // 0..23

    const float *A, *W, *bias, *gam, *bet;
    float* Out; int ld, n0, do_ln, is_q, is_v;
    if (cb < 8) {
        A = g_x1t; W = g_wqt; bias = bq; ld = CC; n0 = cb << 7;
        Out = g_q; do_ln = 1; is_q = 1; is_v = 0; gam = gamq; bet = betq;
    } else {
        int c2 = cb - 8;
        A = g_x2t; W = g_wkvt; bias = bkv; ld = 2 * CC; n0 = c2 << 7; is_q = 0;
        if (c2 < 8) { Out = g_k; do_ln = 1; is_v = 0; gam = gamk; bet = betk; }
        else        { Out = g_v; do_ln = 0; is_v = 1; gam = gamq; bet = betq; }
    }
    int n0w = n0 + (wn << 6);
    int head = (is_v ? (n0w - 1024) : n0w) >> 6;

    float c[4][8][4];
    #pragma unroll
    for (int mf = 0; mf < 4; mf++)
        #pragma unroll
        for (int nf = 0; nf < 8; nf++)
            #pragma unroll
            for (int i = 0; i < 4; i++) c[mf][nf][i] = 0.f;

    uint32_t as_u = smem_u32(As), bs_u = smem_u32(Bs);
    int ar = tid >> 3, ac = tid & 7;
    int br = tid >> 5, bc = tid & 31;
    const float* Ap = A + (size_t)(m0 + ar) * CC + (ac << 2);
    const float* Wp = W + (size_t)br * ld + n0 + (bc << 2);

    // prologue: chunk 0 -> buf0, chunk 1 -> buf1 (two groups in flight)
    #pragma unroll
    for (int i = 0; i < 8; i++) {
        cp16(as_u + ((ar + (i << 4)) * 36 + (ac << 2)) * 4, Ap + (size_t)(i << 4) * CC);
        cp16(bs_u + ((br + (i << 2)) * 136 + (bc << 2)) * 4, Wp + (size_t)(i << 2) * ld);
    }
    cp_commit();
    #pragma unroll
    for (int i = 0; i < 8; i++) {
        cp16(as_u + ((128 + ar + (i << 4)) * 36 + (ac << 2)) * 4,
             Ap + (size_t)(i << 4) * CC + 32);
        cp16(bs_u + ((32 + br + (i << 2)) * 136 + (bc << 2)) * 4,
             Wp + (size_t)(32 + (i << 2)) * ld);
    }
    cp_commit();

    int buf = 0;                       // ch % 3
    for (int ch = 0; ch < 32; ch++) {
        if (ch < 31) cp_wait1();       // drain chunk ch, keep ch+1 in flight
        else         cp_wait0();
        __syncthreads();               // everyone's ch visible; all finished MMA ch-1

        // issue chunk ch+2 into buffer (ch+2)%3 (its readers passed the barrier)
        if (ch < 30) {
            int pb = buf + 2; if (pb >= 3) pb -= 3;
            int k0 = (ch + 2) << 5;
            #pragma unroll
            for (int i = 0; i < 8; i++) {
                cp16(as_u + (((pb << 7) + ar + (i << 4)) * 36 + (ac << 2)) * 4,
                     Ap + (size_t)(i << 4) * CC + k0);
                cp16(bs_u + ((pb * 32 + br + (i << 2)) * 136 + (bc << 2)) * 4,
                     Wp + (size_t)(k0 + (i << 2)) * ld);
            }
            cp_commit();
        }

        float (*Ab)[36]  = &As[buf << 7];
        float (*Bb)[136] = &Bs[buf * 32];
        #pragma unroll
        for (int ks = 0; ks < 4; ks++) {
            int k8 = ks << 3;
            uint32_t a[4][4];
            #pragma unroll
            for (int mf = 0; mf < 4; mf++) {
                int r = (wm << 6) + (mf << 4) + grp;
                a[mf][0] = __float_as_uint(Ab[r][k8 + l4]);
                a[mf][1] = __float_as_uint(Ab[r + 8][k8 + l4]);
                a[mf][2] = __float_as_uint(Ab[r][k8 + l4 + 4]);
                a[mf][3] = __float_as_uint(Ab[r + 8][k8 + l4 + 4]);
            }
            #pragma unroll
            for (int nf = 0; nf < 8; nf++) {
                int n = (wn << 6) + (nf << 3) + grp;
                uint32_t b[2];
                b[0] = __float_as_uint(Bb[k8 + l4][n]);
                b[1] = __float_as_uint(Bb[k8 + l4 + 4][n]);
                #pragma unroll
                for (int mf = 0; mf < 4; mf++)
                    mma8(c[mf][nf], a[mf], b);
            }
        }
        if (++buf == 3) buf = 0;
    }

    // Epilogue: bias + (optional) LN + (q) log2 scale + tf32 float2 stores
    const float SC = 0.18033688011112042f;   // 0.125 * log2(e)
    #pragma unroll
    for (int mf = 0; mf < 4; mf++) {
        float s0 = 0.f, s1 = 0.f, t0 = 0.f, t1 = 0.f;
        #pragma unroll
        for (int nf = 0; nf < 8; nf++) {
            int col = (nf << 3) + (l4 << 1);
            float b0 = bias[n0w + col], b1 = bias[n0w + col + 1];
            c[mf][nf][0] += b0; c[mf][nf][1] += b1;
            c[mf][nf][2] += b0; c[mf][nf][3] += b1;
            s0 += c[mf][nf][0] + c[mf][nf][1];
            s1 += c[mf][nf][2] + c[mf][nf][3];
            t0 += c[mf][nf][0] * c[mf][nf][0] + c[mf][nf][1] * c[mf][nf][1];
            t1 += c[mf][nf][2] * c[mf][nf][2] + c[mf][nf][3] * c[mf][nf][3];
        }
        #pragma unroll
        for (int off = 1; off <= 2; off <<= 1) {
            s0 += __shfl_xor_sync(0xffffffffu, s0, off);
            s1 += __shfl_xor_sync(0xffffffffu, s1, off);
            t0 += __shfl_xor_sync(0xffffffffu, t0, off);
            t1 += __shfl_xor_sync(0xffffffffu, t1, off);
        }
        float mean0 = 0.f, mean1 = 0.f, inv0 = 1.f, inv1 = 1.f;
        if (do_ln) {
            mean0 = s0 * 0.015625f;
            mean1 = s1 * 0.015625f;
            inv0 = rsqrtf(t0 * 0.015625f - mean0 * mean0 + 1e-5f);
            inv1 = rsqrtf(t1 * 0.015625f - mean1 * mean1 + 1e-5f);
        }

        int r0 = (wm << 6) + (mf << 4) + grp;
        int m = m0 + r0;
        int b = m >> 11, nseq = m & 2047;
        size_t base0 = (((size_t)(b * HH + head)) * NN + nseq) * DD;
        size_t base1 = base0 + (size_t)8 * DD;
        #pragma unroll
        for (int nf = 0; nf < 8; nf++) {
            int col = (nf << 3) + (l4 << 1);
            float y0 = c[mf][nf][0], y1 = c[mf][nf][1];
            float y2 = c[mf][nf][2], y3 = c[mf][nf][3];
            if (do_ln) {
                float g0 = gam[col], g1 = gam[col + 1];
                float e0 = bet[col], e1 = bet[col + 1];
                y0 = (y0 - mean0) * inv0 * g0 + e0;
                y1 = (y1 - mean0) * inv0 * g1 + e1;
                y2 = (y2 - mean1) * inv1 * g0 + e0;
                y3 = (y3 - mean1) * inv1 * g1 + e1;
            }
            if (is_q) { y0 *= SC; y1 *= SC; y2 *= SC; y3 *= SC; }
            *(float2*)&Out[base0 + col] = make_float2(f2tf(y0), f2tf(y1));
            *(float2*)&Out[base1 + col] = make_float2(f2tf(y2), f2tf(y3));
        }
    }
}

// ---------------------------------------------------------------------------
// Flash attention (tf32 MMA), unnormalized exp2 accumulation (R9 form).
// Key-permuted K tile -> S-fragment directly the PV A-fragment, no shuffles.
// K/V double-buffered: 2 barriers + 1 wait per iter. 104 KB smem, 2 CTAs/SM.
// ---------------------------------------------------------------------------
#define QS_F (128*68)
#define KS_F (64*68)
#define VS_F (64*72)
#define ATTN_SMEM ((QS_F + 2*KS_F + 2*VS_F) * 4)   // 106496 bytes

__global__ __launch_bounds__(128, 2) void attn_kernel(float* __restrict__ out)
{
    extern __shared__ float sm[];
    float (*Qs)[68] = (float(*)[68])sm;                    // 128x68
    float* Ksb = sm + QS_F;                                // 2 x 64x68
    float* Vsb = sm + QS_F + 2 * KS_F;                     // 2 x 64x72

    int tid = threadIdx.x;
    int wid = tid >> 5, lane = tid & 31;
    int grp = lane >> 2, l4 = lane & 3;
    int bh = blockIdx.y, qt = blockIdx.x;
    int mb = wid << 5;

    const float* qb = g_q + (size_t)bh * (NN * 64) + (size_t)qt * (128 * 64);
    const float* kb = g_k + (size_t)bh * (NN * 64);
    const float* vb = g_v + (size_t)bh * (NN * 64);

    uint32_t qs_u = smem_u32(Qs), ks_u = smem_u32(Ksb), vs_u = smem_u32(Vsb);
    int lr = tid >> 4, lch = tid & 15;
    int slr = ((lr & 3) << 1) | (lr >> 2);   // key permutation within 8-group

    // prologue: Q + K0/V0 (group A), then K1/V1 (group B)
    #pragma unroll
    for (int i = 0; i < 8; i++) {
        int r = lr + (i << 3);
        cp16(qs_u + r * 272 + (lch << 4), qb + r * 64 + (lch << 2));
        cp16(qs_u + (r + 64) * 272 + (lch << 4), qb + (r + 64) * 64 + (lch << 2));
        cp16(ks_u + ((i << 3) + slr) * 272 + (lch << 4), kb + r * 64 + (lch << 2));
        cp16(vs_u + r * 288 + (lch << 4), vb + r * 64 + (lch << 2));
    }
    cp_commit();
    #pragma unroll
    for (int i = 0; i < 8; i++) {
        int r = lr + (i << 3);
        cp16(ks_u + (KS_F + ((i << 3) + slr) * 68 + (lch << 2)) * 4,
             kb + 4096 + r * 64 + (lch << 2));
        cp16(vs_u + (VS_F + r * 72 + (lch << 2)) * 4, vb + 4096 + r * 64 + (lch << 2));
    }
    cp_commit();
    cp_wait1();        // group A complete
    __syncthreads();

    float o[2][8][4];
    #pragma unroll
    for (int mf = 0; mf < 2; mf++)
        #pragma unroll
        for (int df = 0; df < 8; df++)
            #pragma unroll
            for (int i = 0; i < 4; i++) o[mf][df][i] = 0.f;
    float l_i[4] = {0.f, 0.f, 0.f, 0.f};

    for (int kt = 0; kt < 32; kt++) {
        int buf = kt & 1;
        const float* Ks = Ksb + buf * KS_F;   // [64][68]
        const float* Vs = Vsb + buf * VS_F;   // [64][72]

        float s[2][8][4];
        #pragma unroll
        for (int mf = 0; mf < 2; mf++)
            #pragma unroll
            for (int nf = 0; nf < 8; nf++)
                #pragma unroll
                for (int i = 0; i < 4; i++) s[mf][nf][i] = 0.f;

        #pragma unroll
        for (int ks8 = 0; ks8 < 8; ks8++) {
            int k8 = ks8 << 3;
            uint32_t a[2][4], b[8][2];
            #pragma unroll
            for (int mf = 0; mf < 2; mf++) {
                int r = mb + (mf << 4) + grp;
                a[mf][0] = __float_as_uint(Qs[r][k8 + l4]);
                a[mf][1] = __float_as_uint(Qs[r + 8][k8 + l4]);
                a[mf][2] = __float_as_uint(Qs[r][k8 + l4 + 4]);
                a[mf][3] = __float_as_uint(Qs[r + 8][k8 + l4 + 4]);
            }
            #pragma unroll
            for (int nf = 0; nf < 8; nf++) {
                int n = (nf << 3) + grp;
                b[nf][0] = __float_as_uint(Ks[n * 68 + k8 + l4]);
                b[nf][1] = __float_as_uint(Ks[n * 68 + k8 + l4 + 4]);
            }
            #pragma unroll
            for (int mf = 0; mf < 2; mf++)
                #pragma unroll
                for (int nf = 0; nf < 8; nf++)
                    mma8(s[mf][nf], a[mf], b[nf]);
        }

        // p = exp2(s); per-thread row sums
        #pragma unroll
        for (int mf = 0; mf < 2; mf++)
            #pragma unroll
            for (int nf = 0; nf < 8; nf++) {
                float p0 = ex2(s[mf][nf][0]);
                float p1 = ex2(s[mf][nf][1]);
                float p2 = ex2(s[mf][nf][2]);
                float p3 = ex2(s[mf][nf][3]);
                s[mf][nf][0] = p0; s[mf][nf][1] = p1;
                s[mf][nf][2] = p2; s[mf][nf][3] = p3;
                l_i[mf << 1]       += p0 + p1;
                l_i[(mf << 1) + 1] += p2 + p3;
            }

        // O += P @ V: S-fragment IS the A-fragment ({c0,c2,c1,c3})
        #pragma unroll
        for (int g = 0; g < 8; g++) {
            int k8 = g << 3;
            uint32_t b[8][2];
            #pragma unroll
            for (int df = 0; df < 8; df++) {
                int n = (df << 3) + grp;
                b[df][0] = __float_as_uint(Vs[(k8 + l4) * 72 + n]);
                b[df][1] = __float_as_uint(Vs[(k8 + l4 + 4) * 72 + n]);
            }
            #pragma unroll
            for (int mf = 0; mf < 2; mf++) {
                uint32_t a[4];
                a[0] = __float_as_uint(s[mf][g][0]);
                a[1] = __float_as_uint(s[mf][g][2]);
                a[2] = __float_as_uint(s[mf][g][1]);
                a[3] = __float_as_uint(s[mf][g][3]);
                #pragma unroll
                for (int df = 0; df < 8; df++)
                    mma8(o[mf][df], a, b[df]);
            }
        }

        if (kt < 31) {
            __syncthreads();       // all warps done with buf
            if (kt < 30) {
                const float* kn = kb + (kt + 2) * 4096;
                const float* vn = vb + (kt + 2) * 4096;
                uint32_t kdst = ks_u + buf * (KS_F * 4);
                uint32_t vdst = vs_u + buf * (VS_F * 4);
                #pragma unroll
                for (int i = 0; i < 8; i++) {
                    int r = lr + (i << 3);
                    cp16(kdst + ((i << 3) + slr) * 272 + (lch << 4), kn + r * 64 + (lch << 2));
                    cp16(vdst + r * 288 + (lch << 4), vn + r * 64 + (lch << 2));
                }
                cp_commit();
                cp_wait1();        // group kt+1 complete
            } else {
                cp_wait0();
            }
            __syncthreads();       // next buffer visible
        }
    }

    // epilogue: reduce row sums across quad, normalize, write out[b][n][h*64+d]
    #pragma unroll
    for (int si = 0; si < 4; si++) {
        l_i[si] += __shfl_xor_sync(0xffffffffu, l_i[si], 1);
        l_i[si] += __shfl_xor_sync(0xffffffffu, l_i[si], 2);
    }
    int b = bh >> 4, h = bh & 15;
    #pragma unroll
    for (int mf = 0; mf < 2; mf++) {
        #pragma unroll
        for (int rr = 0; rr < 2; rr++) {
            int si = (mf << 1) + rr;
            float inv = 1.f / l_i[si];
            int n = (qt << 7) + mb + (mf << 4) + grp + (rr << 3);
            size_t base = ((size_t)(b * NN + n)) * CC + (h << 6);
            #pragma unroll
            for (int df = 0; df < 8; df++) {
                int col = (df << 3) + (l4 << 1);
                float2 vo = make_float2(o[mf][df][rr * 2] * inv,
                                        o[mf][df][rr * 2 + 1] * inv);
                *(float2*)&out[base + col] = vo;
            }
        }
    }
}

// ---------------------------------------------------------------------------
extern "C" void kernel_launch(void* const* d_in, const int* in_sizes, int n_in,
                              void* d_out, int out_size)
{
    const float* x1   = (const float*)d_in[0];
    const float* x2   = (const float*)d_in[1];
    const float* wq   = (const float*)d_in[2];
    const float* bq   = (const float*)d_in[3];
    const float* wkv  = (const float*)d_in[4];
    const float* bkv  = (const float*)d_in[5];
    const float* gmq  = (const float*)d_in[6];
    const float* btq  = (const float*)d_in[7];
    const float* gmk  = (const float*)d_in[8];
    const float* btk  = (const float*)d_in[9];
    float* out = (float*)d_out;

    cudaFuncSetAttribute(attn_kernel, cudaFuncAttributeMaxDynamicSharedMemorySize, ATTN_SMEM);
    cudaFuncSetAttribute(proj_kernel, cudaFuncAttributeMaxDynamicSharedMemorySize, PROJ_SMEM);

    prep_all<<<19456, 256>>>(x1, x2, wq, wkv);

    proj_kernel<<<dim3(24, MM / 128), 128, PROJ_SMEM>>>(bq, bkv, gmq, btq, gmk, btk);

    attn_kernel<<<dim3(NN / 128, BB * HH), 128, ATTN_SMEM>>>(out);
}

// round 14
// speedup vs baseline: 2.9516x; 1.8530x over previous
#include <cuda_runtime.h>
#include <cuda_fp16.h>
#include <cstdint>

#define BB 4
#define NN 2048
#define CC 1024
#define HH 16
#define DD 64
#define MM (BB*NN)          // 8192

// Scratch (fp16; q,k post-LN; q pre-scaled by 0.125*log2e); [bh][token][d]
__device__ __half g_q[(size_t)MM * CC];
__device__ __half g_k[(size_t)MM * CC];
__device__ __half g_v[(size_t)MM * CC];
// fp16 copies of inputs
__device__ __half g_x1h[(size_t)MM * CC];
__device__ __half g_x2h[(size_t)MM * CC];
__device__ __half g_wqh[(size_t)CC * CC];
__device__ __half g_wkvh[(size_t)CC * 2 * CC];

// ---------------------------------------------------------------------------
// helpers
// ---------------------------------------------------------------------------
__device__ __forceinline__ float ex2(float x) {
    float r;
    asm("ex2.approx.ftz.f32 %0, %1;" : "=f"(r) : "f"(x));
    return r;
}

__device__ __forceinline__ uint32_t packh2(float lo, float hi) {
    __half2 h = __floats2half2_rn(lo, hi);
    return *reinterpret_cast<uint32_t*>(&h);
}

__device__ __forceinline__ uint32_t smem_u32(const void* p) {
    uint32_t a;
    asm("{ .reg .u64 t; cvta.to.shared.u64 t, %1; cvt.u32.u64 %0, t; }" : "=r"(a) : "l"(p));
    return a;
}

__device__ __forceinline__ void cp16(uint32_t dst, const void* src) {
    asm volatile("cp.async.cg.shared.global [%0], [%1], 16;" :: "r"(dst), "l"(src));
}
__device__ __forceinline__ void cp_commit() { asm volatile("cp.async.commit_group;"); }
__device__ __forceinline__ void cp_wait0()  { asm volatile("cp.async.wait_group 0;"); }
__device__ __forceinline__ void cp_wait1()  { asm volatile("cp.async.wait_group 1;"); }

__device__ __forceinline__ void mmah(float c[4], const uint32_t a[4], const uint32_t b[2]) {
    asm volatile(
        "mma.sync.aligned.m16n8k16.row.col.f32.f16.f16.f32 "
        "{%0,%1,%2,%3}, {%4,%5,%6,%7}, {%8,%9}, {%0,%1,%2,%3};\n"
        : "+f"(c[0]), "+f"(c[1]), "+f"(c[2]), "+f"(c[3])
        : "r"(a[0]), "r"(a[1]), "r"(a[2]), "r"(a[3]), "r"(b[0]), "r"(b[1]));
}

__device__ __forceinline__ void ldm2t(uint32_t& r0, uint32_t& r1, uint32_t addr) {
    asm volatile("ldmatrix.sync.aligned.m8n8.x2.trans.shared.b16 {%0,%1}, [%2];"
                 : "=r"(r0), "=r"(r1) : "r"(addr));
}

// ---------------------------------------------------------------------------
// Merged fp32 -> fp16 conversion (x1 | x2 | wq | wkv in one grid)
// block counts (float4 granularity / 256 threads): 8192 | 8192 | 1024 | 2048
// ---------------------------------------------------------------------------
__global__ __launch_bounds__(256) void prep_all(
    const float* __restrict__ x1, const float* __restrict__ x2,
    const float* __restrict__ wq, const float* __restrict__ wkv)
{
    int b = blockIdx.x;
    const float* src; __half* dst; int off;
    if (b < 8192)       { src = x1;  dst = g_x1h;  off = b; }
    else if (b < 16384) { src = x2;  dst = g_x2h;  off = b - 8192; }
    else if (b < 17408) { src = wq;  dst = g_wqh;  off = b - 16384; }
    else                { src = wkv; dst = g_wkvh; off = b - 17408; }
    int i = off * 256 + threadIdx.x;
    float4 v = ((const float4*)src)[i];
    uint2 o;
    o.x = packh2(v.x, v.y);
    o.y = packh2(v.z, v.w);
    ((uint2*)dst)[i] = o;
}

// ---------------------------------------------------------------------------
// Projection GEMM (q + kv in one launch), fp16 m16n8k16 MMA, fp32 accum.
// 3-stage cp.async pipeline (one barrier + one wait per 32-k chunk).
// Block tile 128x128 (2 heads); 4 warps, each 64x64.
// A (x rows) via packed LDS.32; B (W [k][n]) via ldmatrix.x2.trans.
// Epilogue: bias + per-head LN (q,k), q log2-scale, fp16 half2 stores.
// ---------------------------------------------------------------------------
#define PA_ROW 40                       // halves per A row (pad 32->40)
#define PB_ROW 136                      // halves per B row (pad 128->136)
#define ABUF (128*PA_ROW)               // halves
#define BBUF (32*PB_ROW)
#define PROJ_SMEM ((3*ABUF + 3*BBUF) * 2)   // 56832 bytes

__global__ __launch_bounds__(128, 2) void proj_kernel(
    const float* __restrict__ bq, const float* __restrict__ bkv,
    const float* __restrict__ gamq, const float* __restrict__ betq,
    const float* __restrict__ gamk, const float* __restrict__ betk)
{
    extern __shared__ __half smh[];
    __half* Asm = smh;                  // 3 x [128][PA_ROW]
    __half* Bsm = smh + 3 * ABUF;       // 3 x [32][PB_ROW]

    int tid  = threadIdx.x;
    int wid  = tid >> 5, lane = tid & 31;
    int grp  = lane >> 2, l4 = lane & 3;
    int l15  = lane & 15;
    int wm   = wid >> 1, wn = wid & 1;
    int m0   = blockIdx.y << 7;
    int cb   = blockIdx.x;              // 0..23

    const __half *A, *W;
    const float *bias, *gam, *bet;
    __half* Out; int ld, n0, do_ln, is_q;
    if (cb < 8) {
        A = g_x1h; W = g_wqh; bias = bq; ld = CC; n0 = cb << 7;
        Out = g_q; do_ln = 1; is_q = 1; gam = gamq; bet = betq;
    } else {
        int c2 = cb - 8;
        A = g_x2h; W = g_wkvh; bias = bkv; ld = 2 * CC; n0 = c2 << 7; is_q = 0;
        if (c2 < 8) { Out = g_k; do_ln = 1; gam = gamk; bet = betk; }
        else        { Out = g_v; do_ln = 0; gam = gamq; bet = betq; }
    }
    int n0w = n0 + (wn << 6);
    int head = ((cb >= 16) ? (n0w - 1024) : n0w) >> 6;

    float c[4][8][4];
    #pragma unroll
    for (int mf = 0; mf < 4; mf++)
        #pragma unroll
        for (int nf = 0; nf < 8; nf++)
            #pragma unroll
            for (int i = 0; i < 4; i++) c[mf][nf][i] = 0.f;

    uint32_t as_u = smem_u32(Asm), bs_u = smem_u32(Bsm);

    // loaders: A 128 rows x 4 chunks(16B); B 32 rows x 16 chunks
    int aR = tid >> 2, aQ = tid & 3;         // + i*32 rows per pass (4 passes)
    int bR = tid >> 4, bQ = tid & 15;        // + i*8 rows per pass (4 passes)

    // prologue: chunk 0 -> buf0, chunk 1 -> buf1
    #pragma unroll
    for (int i = 0; i < 4; i++) {
        int r = aR + (i << 5);
        cp16(as_u + (r * PA_ROW + (aQ << 3)) * 2, A + (size_t)(m0 + r) * CC + (aQ << 3));
        int rb = bR + (i << 3);
        cp16(bs_u + (rb * PB_ROW + (bQ << 3)) * 2, W + (size_t)rb * ld + n0 + (bQ << 3));
    }
    cp_commit();
    #pragma unroll
    for (int i = 0; i < 4; i++) {
        int r = aR + (i << 5);
        cp16(as_u + (ABUF + r * PA_ROW + (aQ << 3)) * 2,
             A + (size_t)(m0 + r) * CC + 32 + (aQ << 3));
        int rb = bR + (i << 3);
        cp16(bs_u + (BBUF + rb * PB_ROW + (bQ << 3)) * 2,
             W + (size_t)(32 + rb) * ld + n0 + (bQ << 3));
    }
    cp_commit();

    int buf = 0;
    for (int ch = 0; ch < 32; ch++) {
        if (ch < 31) cp_wait1();
        else         cp_wait0();
        __syncthreads();

        if (ch < 30) {
            int pb = buf + 2; if (pb >= 3) pb -= 3;
            int k0 = (ch + 2) << 5;
            #pragma unroll
            for (int i = 0; i < 4; i++) {
                int r = aR + (i << 5);
                cp16(as_u + (pb * ABUF + r * PA_ROW + (aQ << 3)) * 2,
                     A + (size_t)(m0 + r) * CC + k0 + (aQ << 3));
                int rb = bR + (i << 3);
                cp16(bs_u + (pb * BBUF + rb * PB_ROW + (bQ << 3)) * 2,
                     W + (size_t)(k0 + rb) * ld + n0 + (bQ << 3));
            }
            cp_commit();
        }

        const __half* Ab = Asm + buf * ABUF;
        uint32_t bbu = bs_u + (buf * BBUF) * 2;
        #pragma unroll
        for (int kk = 0; kk < 2; kk++) {
            int kc = (kk << 4) + (l4 << 1);
            uint32_t a[4][4];
            #pragma unroll
            for (int mf = 0; mf < 4; mf++) {
                int r = (wm << 6) + (mf << 4) + grp;
                a[mf][0] = *(const uint32_t*)&Ab[r * PA_ROW + kc];
                a[mf][1] = *(const uint32_t*)&Ab[(r + 8) * PA_ROW + kc];
                a[mf][2] = *(const uint32_t*)&Ab[r * PA_ROW + kc + 8];
                a[mf][3] = *(const uint32_t*)&Ab[(r + 8) * PA_ROW + kc + 8];
            }
            #pragma unroll
            for (int nf = 0; nf < 8; nf++) {
                uint32_t b[2];
                ldm2t(b[0], b[1],
                      bbu + (((kk << 4) + l15) * PB_ROW + (wn << 6) + (nf << 3)) * 2);
                #pragma unroll
                for (int mf = 0; mf < 4; mf++)
                    mmah(c[mf][nf], a[mf], b);
            }
        }
        if (++buf == 3) buf = 0;
    }

    // Epilogue: bias + (optional) LN + (q) log2 scale + fp16 half2 stores
    const float SC = 0.18033688011112042f;   // 0.125 * log2(e)
    #pragma unroll
    for (int mf = 0; mf < 4; mf++) {
        float s0 = 0.f, s1 = 0.f, t0 = 0.f, t1 = 0.f;
        #pragma unroll
        for (int nf = 0; nf < 8; nf++) {
            int col = (nf << 3) + (l4 << 1);
            float b0 = bias[n0w + col], b1 = bias[n0w + col + 1];
            c[mf][nf][0] += b0; c[mf][nf][1] += b1;
            c[mf][nf][2] += b0; c[mf][nf][3] += b1;
            s0 += c[mf][nf][0] + c[mf][nf][1];
            s1 += c[mf][nf][2] + c[mf][nf][3];
            t0 += c[mf][nf][0] * c[mf][nf][0] + c[mf][nf][1] * c[mf][nf][1];
            t1 += c[mf][nf][2] * c[mf][nf][2] + c[mf][nf][3] * c[mf][nf][3];
        }
        #pragma unroll
        for (int off = 1; off <= 2; off <<= 1) {
            s0 += __shfl_xor_sync(0xffffffffu, s0, off);
            s1 += __shfl_xor_sync(0xffffffffu, s1, off);
            t0 += __shfl_xor_sync(0xffffffffu, t0, off);
            t1 += __shfl_xor_sync(0xffffffffu, t1, off);
        }
        float mean0 = 0.f, mean1 = 0.f, inv0 = 1.f, inv1 = 1.f;
        if (do_ln) {
            mean0 = s0 * 0.015625f;
            mean1 = s1 * 0.015625f;
            inv0 = rsqrtf(t0 * 0.015625f - mean0 * mean0 + 1e-5f);
            inv1 = rsqrtf(t1 * 0.015625f - mean1 * mean1 + 1e-5f);
        }

        int r0 = (wm << 6) + (mf << 4) + grp;
        int m = m0 + r0;
        int b = m >> 11, nseq = m & 2047;
        size_t base0 = (((size_t)(b * HH + head)) * NN + nseq) * DD;
        size_t base1 = base0 + (size_t)8 * DD;
        #pragma unroll
        for (int nf = 0; nf < 8; nf++) {
            int col = (nf << 3) + (l4 << 1);
            float y0 = c[mf][nf][0], y1 = c[mf][nf][1];
            float y2 = c[mf][nf][2], y3 = c[mf][nf][3];
            if (do_ln) {
                float g0 = gam[col], g1 = gam[col + 1];
                float e0 = bet[col], e1 = bet[col + 1];
                y0 = (y0 - mean0) * inv0 * g0 + e0;
                y1 = (y1 - mean0) * inv0 * g1 + e1;
                y2 = (y2 - mean1) * inv1 * g0 + e0;
                y3 = (y3 - mean1) * inv1 * g1 + e1;
            }
            if (is_q) { y0 *= SC; y1 *= SC; y2 *= SC; y3 *= SC; }
            *(uint32_t*)&Out[base0 + col] = packh2(y0, y1);
            *(uint32_t*)&Out[base1 + col] = packh2(y2, y3);
        }
    }
}

// ---------------------------------------------------------------------------
// Flash attention (fp16 m16n8k16 MMA, fp32 accum), unnormalized exp2.
// Q/K fragments via packed LDS.32 (natural [token][d]); V via ldmatrix.trans.
// S-accumulator packs directly into the PV A-fragment (adjacent pairs).
// K/V double-buffered: 2 barriers + 1 wait per iter. 54 KB smem, 2 CTAs/SM.
// ---------------------------------------------------------------------------
#define AROW 72                         // halves per smem row (pad 64->72)
#define QS_H (128*AROW)
#define KS_H (64*AROW)
#define VS_H (64*AROW)
#define ATTN_SMEM ((QS_H + 2*KS_H + 2*VS_H) * 2)   // 55296 bytes

__global__ __launch_bounds__(128, 2) void attn_kernel(float* __restrict__ out)
{
    extern __shared__ __half smh[];
    __half* Qs  = smh;                  // [128][AROW]
    __half* Ksb = smh + QS_H;           // 2 x [64][AROW]
    __half* Vsb = smh + QS_H + 2 * KS_H;

    int tid = threadIdx.x;
    int wid = tid >> 5, lane = tid & 31;
    int grp = lane >> 2, l4 = lane & 3;
    int l15 = lane & 15;
    int bh = blockIdx.y, qt = blockIdx.x;
    int mb = wid << 5;

    const __half* qb = g_q + (size_t)bh * (NN * 64) + (size_t)qt * (128 * 64);
    const __half* kb = g_k + (size_t)bh * (NN * 64);
    const __half* vb = g_v + (size_t)bh * (NN * 64);

    uint32_t qs_u = smem_u32(Qs), ks_u = smem_u32(Ksb), vs_u = smem_u32(Vsb);

    // prologue: Q + K0/V0 (group A), then K1/V1 (group B)
    #pragma unroll
    for (int i = 0; i < 8; i++) {
        int f = i * 128 + tid;
        int r = f >> 3, q = f & 7;
        cp16(qs_u + (r * AROW + (q << 3)) * 2, qb + r * 64 + (q << 3));
    }
    #pragma unroll
    for (int i = 0; i < 4; i++) {
        int f = i * 128 + tid;
        int r = f >> 3, q = f & 7;
        cp16(ks_u + (r * AROW + (q << 3)) * 2, kb + r * 64 + (q << 3));
        cp16(vs_u + (r * AROW + (q << 3)) * 2, vb + r * 64 + (q << 3));
    }
    cp_commit();
    #pragma unroll
    for (int i = 0; i < 4; i++) {
        int f = i * 128 + tid;
        int r = f >> 3, q = f & 7;
        cp16(ks_u + (KS_H + r * AROW + (q << 3)) * 2, kb + 4096 + r * 64 + (q << 3));
        cp16(vs_u + (VS_H + r * AROW + (q << 3)) * 2, vb + 4096 + r * 64 + (q << 3));
    }
    cp_commit();
    cp_wait1();        // group A complete
    __syncthreads();

    float o[2][8][4];
    #pragma unroll
    for (int mf = 0; mf < 2; mf++)
        #pragma unroll
        for (int df = 0; df < 8; df++)
            #pragma unroll
            for (int i = 0; i < 4; i++) o[mf][df][i] = 0.f;
    float l_i[4] = {0.f, 0.f, 0.f, 0.f};

    for (int kt = 0; kt < 32; kt++) {
        int buf = kt & 1;
        const __half* Ks = Ksb + buf * KS_H;
        uint32_t vbu = vs_u + (buf * VS_H) * 2;

        // S = Q @ K^T (log2 domain)
        float s[2][8][4];
        #pragma unroll
        for (int mf = 0; mf < 2; mf++)
            #pragma unroll
            for (int nf = 0; nf < 8; nf++)
                #pragma unroll
                for (int i = 0; i < 4; i++) s[mf][nf][i] = 0.f;

        #pragma unroll
        for (int kk = 0; kk < 4; kk++) {
            int kc = (kk << 4) + (l4 << 1);
            uint32_t a[2][4], b[8][2];
            #pragma unroll
            for (int mf = 0; mf < 2; mf++) {
                int r = mb + (mf << 4) + grp;
                a[mf][0] = *(const uint32_t*)&Qs[r * AROW + kc];
                a[mf][1] = *(const uint32_t*)&Qs[(r + 8) * AROW + kc];
                a[mf][2] = *(const uint32_t*)&Qs[r * AROW + kc + 8];
                a[mf][3] = *(const uint32_t*)&Qs[(r + 8) * AROW + kc + 8];
            }
            #pragma unroll
            for (int nf = 0; nf < 8; nf++) {
                int n = (nf << 3) + grp;
                b[nf][0] = *(const uint32_t*)&Ks[n * AROW + kc];
                b[nf][1] = *(const uint32_t*)&Ks[n * AROW + kc + 8];
            }
            #pragma unroll
            for (int mf = 0; mf < 2; mf++)
                #pragma unroll
                for (int nf = 0; nf < 8; nf++)
                    mmah(s[mf][nf], a[mf], b[nf]);
        }

        // p = exp2(s); per-thread row sums
        #pragma unroll
        for (int mf = 0; mf < 2; mf++)
            #pragma unroll
            for (int nf = 0; nf < 8; nf++) {
                float p0 = ex2(s[mf][nf][0]);
                float p1 = ex2(s[mf][nf][1]);
                float p2 = ex2(s[mf][nf][2]);
                float p3 = ex2(s[mf][nf][3]);
                s[mf][nf][0] = p0; s[mf][nf][1] = p1;
                s[mf][nf][2] = p2; s[mf][nf][3] = p3;
                l_i[mf << 1]       += p0 + p1;
                l_i[(mf << 1) + 1] += p2 + p3;
            }

        // O += P @ V : P packed from S regs; V b-frags via ldmatrix.trans
        #pragma unroll
        for (int kk = 0; kk < 4; kk++) {
            uint32_t b[8][2];
            #pragma unroll
            for (int df = 0; df < 8; df++)
                ldm2t(b[df][0], b[df][1],
                      vbu + (((kk << 4) + l15) * AROW + (df << 3)) * 2);
            #pragma unroll
            for (int mf = 0; mf < 2; mf++) {
                uint32_t a[4];
                a[0] = packh2(s[mf][kk << 1][0],        s[mf][kk << 1][1]);
                a[1] = packh2(s[mf][kk << 1][2],        s[mf][kk << 1][3]);
                a[2] = packh2(s[mf][(kk << 1) + 1][0],  s[mf][(kk << 1) + 1][1]);
                a[3] = packh2(s[mf][(kk << 1) + 1][2],  s[mf][(kk << 1) + 1][3]);
                #pragma unroll
                for (int df = 0; df < 8; df++)
                    mmah(o[mf][df], a, b[df]);
            }
        }

        if (kt < 31) {
            __syncthreads();       // all warps done with buf
            if (kt < 30) {
                const __half* kn = kb + (kt + 2) * 4096;
                const __half* vn = vb + (kt + 2) * 4096;
                uint32_t kdst = ks_u + (buf * KS_H) * 2;
                uint32_t vdst = vs_u + (buf * VS_H) * 2;
                #pragma unroll
                for (int i = 0; i < 4; i++) {
                    int f = i * 128 + tid;
                    int r = f >> 3, q = f & 7;
                    cp16(kdst + (r * AROW + (q << 3)) * 2, kn + r * 64 + (q << 3));
                    cp16(vdst + (r * AROW + (q << 3)) * 2, vn + r * 64 + (q << 3));
                }
                cp_commit();
                cp_wait1();        // group kt+1 complete
            } else {
                cp_wait0();
            }
            __syncthreads();       // next buffer visible
        }
    }

    // epilogue: reduce row sums across quad, normalize, write out[b][n][h*64+d]
    #pragma unroll
    for (int si = 0; si < 4; si++) {
        l_i[si] += __shfl_xor_sync(0xffffffffu, l_i[si], 1);
        l_i[si] += __shfl_xor_sync(0xffffffffu, l_i[si], 2);
    }
    int b = bh >> 4, h = bh & 15;
    #pragma unroll
    for (int mf = 0; mf < 2; mf++) {
        #pragma unroll
        for (int rr = 0; rr < 2; rr++) {
            int si = (mf << 1) + rr;
            float inv = 1.f / l_i[si];
            int n = (qt << 7) + mb + (mf << 4) + grp + (rr << 3);
            size_t base = ((size_t)(b * NN + n)) * CC + (h << 6);
            #pragma unroll
            for (int df = 0; df < 8; df++) {
                int col = (df << 3) + (l4 << 1);
                float2 vo = make_float2(o[mf][df][rr * 2] * inv,
                                        o[mf][df][rr * 2 + 1] * inv);
                *(float2*)&out[base + col] = vo;
            }
        }
    }
}

// ---------------------------------------------------------------------------
extern "C" void kernel_launch(void* const* d_in, const int* in_sizes, int n_in,
                              void* d_out, int out_size)
{
    const float* x1   = (const float*)d_in[0];
    const float* x2   = (const float*)d_in[1];
    const float* wq   = (const float*)d_in[2];
    const float* bq   = (const float*)d_in[3];
    const float* wkv  = (const float*)d_in[4];
    const float* bkv  = (const float*)d_in[5];
    const float* gmq  = (const float*)d_in[6];
    const float* btq  = (const float*)d_in[7];
    const float* gmk  = (const float*)d_in[8];
    const float* btk  = (const float*)d_in[9];
    float* out = (float*)d_out;

    cudaFuncSetAttribute(attn_kernel, cudaFuncAttributeMaxDynamicSharedMemorySize, ATTN_SMEM);
    cudaFuncSetAttribute(proj_kernel, cudaFuncAttributeMaxDynamicSharedMemorySize, PROJ_SMEM);

    prep_all<<<19456, 256>>>(x1, x2, wq, wkv);

    proj_kernel<<<dim3(24, MM / 128), 128, PROJ_SMEM>>>(bq, bkv, gmq, btq, gmk, btk);

    attn_kernel<<<dim3(NN / 128, BB * HH), 128, ATTN_SMEM>>>(out);
}